// round 2
// baseline (speedup 1.0000x reference)
#include <cuda_runtime.h>
#include <cuda_bf16.h>
#include <stdint.h>

#define NLAYER 15

// Fragment-ordered, pre-split weights: [layer][p=hi/lo][chunk(kt*8+nt2)][lane] uint4
// Each uint4 = B fragments for one (k16 x n16) chunk: {b0,b1} of ntile 2*nt2, {b0,b1} of 2*nt2+1
__device__ __align__(128) uint4 g_wfrag[NLAYER][2][64][32];

// ---------------- smem layout ----------------
#define SO_FULL0  0
#define SO_FULL1  8
#define SO_W1     64                  // 256 floats
#define SO_B1     1088                // 128 floats
#define SO_W17    1600                // 128 floats
#define SO_BIAS   2112                // 15*128 floats = 7680 B
#define SO_WBUF   10240               // 1024-aligned; 2 x 65536 double buffer
#define SMEM_TOTAL (10240 + 2*65536)  // 141312 B

// ---------------- helpers ----------------
__device__ __forceinline__ uint32_t smem_u32(const void* p) {
    uint32_t a;
    asm("{ .reg .u64 t; cvta.to.shared.u64 t, %1; cvt.u32.u64 %0, t; }" : "=r"(a) : "l"(p));
    return a;
}
__device__ __forceinline__ void mbar_init(uint32_t mbar, uint32_t cnt) {
    asm volatile("mbarrier.init.shared.b64 [%0], %1;" :: "r"(mbar), "r"(cnt) : "memory");
}
__device__ __forceinline__ void mbar_expect_tx(uint32_t mbar, uint32_t bytes) {
    asm volatile("mbarrier.arrive.expect_tx.shared.b64 _, [%0], %1;" :: "r"(mbar), "r"(bytes) : "memory");
}
__device__ __forceinline__ void mbar_wait(uint32_t mbar, uint32_t parity) {
    asm volatile(
        "{\n\t.reg .pred P;\n\t"
        "WL_%=:\n\t"
        "mbarrier.try_wait.parity.acquire.cta.shared::cta.b64 P, [%0], %1, 0x989680;\n\t"
        "@P bra WD_%=;\n\t"
        "bra.uni WL_%=;\n\t"
        "WD_%=:\n\t}"
        :: "r"(mbar), "r"(parity) : "memory");
}
__device__ __forceinline__ void bulk_g2s(uint32_t dst, const void* src, uint32_t bytes, uint32_t mbar) {
    asm volatile("cp.async.bulk.shared::cta.global.mbarrier::complete_tx::bytes [%0], [%1], %2, [%3];"
                 :: "r"(dst), "l"(src), "r"(bytes), "r"(mbar) : "memory");
}
__device__ __forceinline__ uint4 lds128(uint32_t addr) {
    uint4 v;
    asm volatile("ld.shared.v4.b32 {%0,%1,%2,%3}, [%4];"
                 : "=r"(v.x), "=r"(v.y), "=r"(v.z), "=r"(v.w) : "r"(addr));
    return v;
}
// mma.sync m16n8k16 bf16 (baseline PTX, assembles for plain sm_103; SASS = HMMA)
__device__ __forceinline__ void mma16816(float* d, const uint32_t* a, uint32_t b0, uint32_t b1) {
    asm volatile(
        "mma.sync.aligned.m16n8k16.row.col.f32.bf16.bf16.f32 "
        "{%0,%1,%2,%3}, {%4,%5,%6,%7}, {%8,%9}, {%0,%1,%2,%3};"
        : "+f"(d[0]), "+f"(d[1]), "+f"(d[2]), "+f"(d[3])
        : "r"(a[0]), "r"(a[1]), "r"(a[2]), "r"(a[3]), "r"(b0), "r"(b1));
}
// split two fp32 into packed bf16 hi pair + packed bf16 lo (residual) pair
__device__ __forceinline__ void split2(float a, float b, uint32_t& hi, uint32_t& lo) {
    __nv_bfloat162 h = __float22bfloat162_rn(make_float2(a, b));
    hi = *reinterpret_cast<uint32_t*>(&h);
    float ra = a - __bfloat162float(h.x);
    float rb = b - __bfloat162float(h.y);
    __nv_bfloat162 l = __float22bfloat162_rn(make_float2(ra, rb));
    lo = *reinterpret_cast<uint32_t*>(&l);
}

// ---------------- prep: split weights into per-lane fragment layout ----------------
__global__ void prep_weights(const float* __restrict__ Ws) {
    int idx = blockIdx.x * blockDim.x + threadIdx.x;
    if (idx >= NLAYER * 2 * 64 * 32) return;
    int lane  = idx & 31;
    int chunk = (idx >> 5) & 63;
    int p     = (idx >> 11) & 1;
    int layer = idx >> 12;
    int kt  = chunk >> 3;
    int nt2 = chunk & 7;
    int tig = lane & 3;
    int g   = lane >> 2;
    int k0 = kt * 16 + tig * 2;
    int n0 = nt2 * 16 + g;
    const float* W = Ws + layer * 16384;

    auto cv = [&](int k, int n) -> uint16_t {
        float w = W[k * 128 + n];
        __nv_bfloat16 h = __float2bfloat16_rn(w);
        __nv_bfloat16 r = p ? __float2bfloat16_rn(w - __bfloat162float(h)) : h;
        return *reinterpret_cast<uint16_t*>(&r);
    };
    auto pk = [](uint16_t lo16, uint16_t hi16) -> uint32_t {
        return (uint32_t)lo16 | ((uint32_t)hi16 << 16);
    };
    uint4 r;
    r.x = pk(cv(k0,     n0),     cv(k0 + 1, n0));
    r.y = pk(cv(k0 + 8, n0),     cv(k0 + 9, n0));
    r.z = pk(cv(k0,     n0 + 8), cv(k0 + 1, n0 + 8));
    r.w = pk(cv(k0 + 8, n0 + 8), cv(k0 + 9, n0 + 8));
    g_wfrag[layer][p][chunk][lane] = r;
}

// ---------------- main fused MLP kernel ----------------
__global__ void __launch_bounds__(256, 1)
mlp_kernel(const float* __restrict__ x, const float* __restrict__ W1,
           const float* __restrict__ b1, const float* __restrict__ bs,
           const float* __restrict__ W17, const float* __restrict__ b17,
           float* __restrict__ out) {
    extern __shared__ __align__(1024) unsigned char smem[];
    uint32_t sb = smem_u32(smem);
    int tid  = threadIdx.x;
    int wid  = tid >> 5;
    int lane = tid & 31;
    int g    = lane >> 2;   // row group within warp tile
    int tig  = lane & 3;    // thread-in-group (column pair selector)

    float* sW1  = reinterpret_cast<float*>(smem + SO_W1);
    float* sB1  = reinterpret_cast<float*>(smem + SO_B1);
    float* sW17 = reinterpret_cast<float*>(smem + SO_W17);
    float* sBias= reinterpret_cast<float*>(smem + SO_BIAS);

    if (tid == 0) {
        mbar_init(sb + SO_FULL0, 1);
        mbar_init(sb + SO_FULL1, 1);
    }
    // stage small tables
    if (tid < 256) sW1[tid] = W1[tid];
    if (tid < 128) { sB1[tid] = b1[tid]; sW17[tid] = W17[tid]; }
    for (int idx = tid; idx < NLAYER * 128; idx += 256) sBias[idx] = bs[idx];
    __syncthreads();

    if (tid == 0) {
        mbar_expect_tx(sb + SO_FULL0, 65536);
        bulk_g2s(sb + SO_WBUF,         &g_wfrag[0][0][0][0], 65536, sb + SO_FULL0);
        mbar_expect_tx(sb + SO_FULL1, 65536);
        bulk_g2s(sb + SO_WBUF + 65536, &g_wfrag[1][0][0][0], 65536, sb + SO_FULL1);
    }

    float b17v = b17[0];

    // ---- fc1: build A fragments (16 rows per warp) directly in registers ----
    size_t p0 = (size_t)blockIdx.x * 128 + (size_t)(wid * 16 + g);
    float2 xa = reinterpret_cast<const float2*>(x)[p0];       // row g
    float2 xb = reinterpret_cast<const float2*>(x)[p0 + 8];   // row g+8

    uint32_t Ahi[8][4], Alo[8][4];
#pragma unroll
    for (int kt = 0; kt < 8; kt++) {
        int c = kt * 16 + tig * 2;
        float va0 = fmaxf(fmaf(xa.x, sW1[c],     fmaf(xa.y, sW1[128 + c],     sB1[c])),     0.f);
        float va1 = fmaxf(fmaf(xa.x, sW1[c + 1], fmaf(xa.y, sW1[128 + c + 1], sB1[c + 1])), 0.f);
        float vb0 = fmaxf(fmaf(xb.x, sW1[c],     fmaf(xb.y, sW1[128 + c],     sB1[c])),     0.f);
        float vb1 = fmaxf(fmaf(xb.x, sW1[c + 1], fmaf(xb.y, sW1[128 + c + 1], sB1[c + 1])), 0.f);
        float va2 = fmaxf(fmaf(xa.x, sW1[c + 8], fmaf(xa.y, sW1[128 + c + 8], sB1[c + 8])), 0.f);
        float va3 = fmaxf(fmaf(xa.x, sW1[c + 9], fmaf(xa.y, sW1[128 + c + 9], sB1[c + 9])), 0.f);
        float vb2 = fmaxf(fmaf(xb.x, sW1[c + 8], fmaf(xb.y, sW1[128 + c + 8], sB1[c + 8])), 0.f);
        float vb3 = fmaxf(fmaf(xb.x, sW1[c + 9], fmaf(xb.y, sW1[128 + c + 9], sB1[c + 9])), 0.f);
        split2(va0, va1, Ahi[kt][0], Alo[kt][0]);
        split2(vb0, vb1, Ahi[kt][1], Alo[kt][1]);
        split2(va2, va3, Ahi[kt][2], Alo[kt][2]);
        split2(vb2, vb3, Ahi[kt][3], Alo[kt][3]);
    }

    float D[16][4];
#pragma unroll
    for (int nt = 0; nt < 16; nt++)
#pragma unroll
        for (int q = 0; q < 4; q++) D[nt][q] = 0.f;

    for (int i = 0; i < NLAYER; i++) {
        mbar_wait(sb + SO_FULL0 + 8 * (i & 1), (uint32_t)((i >> 1) & 1));
        uint32_t wb = sb + SO_WBUF + (uint32_t)(i & 1) * 65536u + (uint32_t)lane * 16u;

        // 3-pass split-bf16 GEMM: D = Ahi*Whi + Alo*Whi + Ahi*Wlo
#pragma unroll
        for (int kt = 0; kt < 8; kt++) {
#pragma unroll
            for (int nt2 = 0; nt2 < 8; nt2++) {
                uint32_t off = (uint32_t)((kt * 8 + nt2) * 512);
                uint4 whi = lds128(wb + off);
                uint4 wlo = lds128(wb + 32768u + off);
                mma16816(D[2 * nt2],     Ahi[kt], whi.x, whi.y);
                mma16816(D[2 * nt2 + 1], Ahi[kt], whi.z, whi.w);
                mma16816(D[2 * nt2],     Alo[kt], whi.x, whi.y);
                mma16816(D[2 * nt2 + 1], Alo[kt], whi.z, whi.w);
                mma16816(D[2 * nt2],     Ahi[kt], wlo.x, wlo.y);
                mma16816(D[2 * nt2 + 1], Ahi[kt], wlo.z, wlo.w);
            }
        }
        __syncthreads();  // all warps done reading buffer (i&1)
        if (tid == 0 && i + 2 < NLAYER) {
            uint32_t fb = sb + SO_FULL0 + 8 * (i & 1);
            mbar_expect_tx(fb, 65536);
            bulk_g2s(sb + SO_WBUF + (uint32_t)(i & 1) * 65536u,
                     &g_wfrag[i + 2][0][0][0], 65536, fb);
        }

        if (i < NLAYER - 1) {
            // epilogue: bias + relu + register-local repack D -> next A fragments
            const float* bi = sBias + i * 128 + tig * 2;
#pragma unroll
            for (int nt = 0; nt < 16; nt++) {
                float2 bb = *reinterpret_cast<const float2*>(bi + nt * 8);
                float v0 = fmaxf(D[nt][0] + bb.x, 0.f);
                float v1 = fmaxf(D[nt][1] + bb.y, 0.f);
                float v2 = fmaxf(D[nt][2] + bb.x, 0.f);
                float v3 = fmaxf(D[nt][3] + bb.y, 0.f);
                int kt = nt >> 1, rp = (nt & 1) * 2;
                split2(v0, v1, Ahi[kt][rp],     Alo[kt][rp]);
                split2(v2, v3, Ahi[kt][rp + 1], Alo[kt][rp + 1]);
                D[nt][0] = 0.f; D[nt][1] = 0.f; D[nt][2] = 0.f; D[nt][3] = 0.f;
            }
        } else {
            // fc17: dot with W17 + shfl reduce over the 4-lane column groups
            const float* bi = sBias + i * 128 + tig * 2;
            const float* w7 = sW17 + tig * 2;
            float s0 = 0.f, s1 = 0.f;
#pragma unroll
            for (int nt = 0; nt < 16; nt++) {
                float2 bb = *reinterpret_cast<const float2*>(bi + nt * 8);
                float2 w2 = *reinterpret_cast<const float2*>(w7 + nt * 8);
                float v0 = fmaxf(D[nt][0] + bb.x, 0.f);
                float v1 = fmaxf(D[nt][1] + bb.y, 0.f);
                float v2 = fmaxf(D[nt][2] + bb.x, 0.f);
                float v3 = fmaxf(D[nt][3] + bb.y, 0.f);
                s0 = fmaf(v0, w2.x, fmaf(v1, w2.y, s0));
                s1 = fmaf(v2, w2.x, fmaf(v3, w2.y, s1));
            }
            s0 += __shfl_xor_sync(0xFFFFFFFFu, s0, 1);
            s0 += __shfl_xor_sync(0xFFFFFFFFu, s0, 2);
            s1 += __shfl_xor_sync(0xFFFFFFFFu, s1, 1);
            s1 += __shfl_xor_sync(0xFFFFFFFFu, s1, 2);
            if (tig == 0) {
                out[p0]     = s0 + b17v;
                out[p0 + 8] = s1 + b17v;
            }
        }
    }
}

// ---------------- launch ----------------
extern "C" void kernel_launch(void* const* d_in, const int* in_sizes, int n_in,
                              void* d_out, int out_size) {
    const float* x   = (const float*)d_in[0];
    const float* W1  = (const float*)d_in[1];
    const float* b1  = (const float*)d_in[2];
    const float* Ws  = (const float*)d_in[3];
    const float* bs  = (const float*)d_in[4];
    const float* W17 = (const float*)d_in[5];
    const float* b17 = (const float*)d_in[6];
    float* out = (float*)d_out;

    cudaFuncSetAttribute(mlp_kernel, cudaFuncAttributeMaxDynamicSharedMemorySize, SMEM_TOTAL);

    int npts = in_sizes[0] / 2;
    int nblk = npts / 128;

    prep_weights<<<(NLAYER * 2 * 64 * 32 + 255) / 256, 256>>>(Ws);
    mlp_kernel<<<nblk, 256, SMEM_TOTAL>>>(x, W1, b1, bs, W17, b17, out);
}

// round 3
// speedup vs baseline: 1.0840x; 1.0840x over previous
#include <cuda_runtime.h>
#include <cuda_bf16.h>
#include <stdint.h>

#define NLAYER 15
#define NBUF   3

// Fragment-ordered, pre-split weights: [layer][p=hi/lo][chunk(kt*8+nt2)][lane] uint4
__device__ __align__(128) uint4 g_wfrag[NLAYER][2][64][32];

// ---------------- smem layout ----------------
#define SO_FULL   0                   // 3 mbarriers x 8B
#define SO_CNT    32                  // 15 uint32 counters
#define SO_W1     128                 // 256 floats
#define SO_B1     1152                // 128 floats
#define SO_W17    1664                // 128 floats
#define SO_BIAS   2176                // 15*128 floats = 7680 B
#define SO_WBUF   10240               // 1024-aligned; 3 x 65536 triple buffer
#define SMEM_TOTAL (10240 + NBUF*65536)   // 206848 B

// ---------------- helpers ----------------
__device__ __forceinline__ uint32_t smem_u32(const void* p) {
    uint32_t a;
    asm("{ .reg .u64 t; cvta.to.shared.u64 t, %1; cvt.u32.u64 %0, t; }" : "=r"(a) : "l"(p));
    return a;
}
__device__ __forceinline__ void mbar_init(uint32_t mbar, uint32_t cnt) {
    asm volatile("mbarrier.init.shared.b64 [%0], %1;" :: "r"(mbar), "r"(cnt) : "memory");
}
__device__ __forceinline__ void mbar_expect_tx(uint32_t mbar, uint32_t bytes) {
    asm volatile("mbarrier.arrive.expect_tx.shared.b64 _, [%0], %1;" :: "r"(mbar), "r"(bytes) : "memory");
}
__device__ __forceinline__ void mbar_wait(uint32_t mbar, uint32_t parity) {
    asm volatile(
        "{\n\t.reg .pred P;\n\t"
        "WL_%=:\n\t"
        "mbarrier.try_wait.parity.acquire.cta.shared::cta.b64 P, [%0], %1, 0x989680;\n\t"
        "@P bra WD_%=;\n\t"
        "bra.uni WL_%=;\n\t"
        "WD_%=:\n\t}"
        :: "r"(mbar), "r"(parity) : "memory");
}
__device__ __forceinline__ void bulk_g2s(uint32_t dst, const void* src, uint32_t bytes, uint32_t mbar) {
    asm volatile("cp.async.bulk.shared::cta.global.mbarrier::complete_tx::bytes [%0], [%1], %2, [%3];"
                 :: "r"(dst), "l"(src), "r"(bytes), "r"(mbar) : "memory");
}
__device__ __forceinline__ uint32_t atom_inc_acqrel(uint32_t addr) {
    uint32_t old;
    asm volatile("atom.acq_rel.cta.shared::cta.add.u32 %0, [%1], 1;"
                 : "=r"(old) : "r"(addr) : "memory");
    return old;
}
__device__ __forceinline__ uint4 lds128(uint32_t addr) {
    uint4 v;
    asm volatile("ld.shared.v4.b32 {%0,%1,%2,%3}, [%4];"
                 : "=r"(v.x), "=r"(v.y), "=r"(v.z), "=r"(v.w) : "r"(addr));
    return v;
}
__device__ __forceinline__ void mma16816(float* d, const uint32_t* a, uint32_t b0, uint32_t b1) {
    asm volatile(
        "mma.sync.aligned.m16n8k16.row.col.f32.bf16.bf16.f32 "
        "{%0,%1,%2,%3}, {%4,%5,%6,%7}, {%8,%9}, {%0,%1,%2,%3};"
        : "+f"(d[0]), "+f"(d[1]), "+f"(d[2]), "+f"(d[3])
        : "r"(a[0]), "r"(a[1]), "r"(a[2]), "r"(a[3]), "r"(b0), "r"(b1));
}
__device__ __forceinline__ void split2(float a, float b, uint32_t& hi, uint32_t& lo) {
    __nv_bfloat162 h = __float22bfloat162_rn(make_float2(a, b));
    hi = *reinterpret_cast<uint32_t*>(&h);
    float ra = a - __bfloat162float(h.x);
    float rb = b - __bfloat162float(h.y);
    __nv_bfloat162 l = __float22bfloat162_rn(make_float2(ra, rb));
    lo = *reinterpret_cast<uint32_t*>(&l);
}

// ---------------- prep: split weights into per-lane fragment layout ----------------
__global__ void prep_weights(const float* __restrict__ Ws) {
    int idx = blockIdx.x * blockDim.x + threadIdx.x;
    if (idx >= NLAYER * 2 * 64 * 32) return;
    int lane  = idx & 31;
    int chunk = (idx >> 5) & 63;
    int p     = (idx >> 11) & 1;
    int layer = idx >> 12;
    int kt  = chunk >> 3;
    int nt2 = chunk & 7;
    int tig = lane & 3;
    int g   = lane >> 2;
    int k0 = kt * 16 + tig * 2;
    int n0 = nt2 * 16 + g;
    const float* W = Ws + layer * 16384;

    auto cv = [&](int k, int n) -> uint16_t {
        float w = W[k * 128 + n];
        __nv_bfloat16 h = __float2bfloat16_rn(w);
        __nv_bfloat16 r = p ? __float2bfloat16_rn(w - __bfloat162float(h)) : h;
        return *reinterpret_cast<uint16_t*>(&r);
    };
    auto pk = [](uint16_t lo16, uint16_t hi16) -> uint32_t {
        return (uint32_t)lo16 | ((uint32_t)hi16 << 16);
    };
    uint4 r;
    r.x = pk(cv(k0,     n0),     cv(k0 + 1, n0));
    r.y = pk(cv(k0 + 8, n0),     cv(k0 + 9, n0));
    r.z = pk(cv(k0,     n0 + 8), cv(k0 + 1, n0 + 8));
    r.w = pk(cv(k0 + 8, n0 + 8), cv(k0 + 9, n0 + 8));
    g_wfrag[layer][p][chunk][lane] = r;
}

// ---------------- main fused MLP kernel ----------------
__global__ void __launch_bounds__(256, 1)
mlp_kernel(const float* __restrict__ x, const float* __restrict__ W1,
           const float* __restrict__ b1, const float* __restrict__ bs,
           const float* __restrict__ W17, const float* __restrict__ b17,
           float* __restrict__ out) {
    extern __shared__ __align__(1024) unsigned char smem[];
    uint32_t sb = smem_u32(smem);
    int tid  = threadIdx.x;
    int wid  = tid >> 5;
    int lane = tid & 31;
    int g    = lane >> 2;   // row group within warp tile
    int tig  = lane & 3;    // thread-in-group (column pair selector)

    float* sW1  = reinterpret_cast<float*>(smem + SO_W1);
    float* sB1  = reinterpret_cast<float*>(smem + SO_B1);
    float* sW17 = reinterpret_cast<float*>(smem + SO_W17);
    float* sBias= reinterpret_cast<float*>(smem + SO_BIAS);
    uint32_t* sCnt = reinterpret_cast<uint32_t*>(smem + SO_CNT);

    if (tid == 0) {
        mbar_init(sb + SO_FULL,      1);
        mbar_init(sb + SO_FULL + 8,  1);
        mbar_init(sb + SO_FULL + 16, 1);
    }
    // stage small tables + zero counters
    if (tid < 256) sW1[tid] = W1[tid];
    if (tid < 128) { sB1[tid] = b1[tid]; sW17[tid] = W17[tid]; }
    if (tid < NLAYER) sCnt[tid] = 0;
    for (int idx = tid; idx < NLAYER * 128; idx += 256) sBias[idx] = bs[idx];
    __syncthreads();

    if (tid == 0) {
#pragma unroll
        for (int j = 0; j < NBUF; j++) {
            mbar_expect_tx(sb + SO_FULL + 8u * j, 65536);
            bulk_g2s(sb + SO_WBUF + 65536u * j, &g_wfrag[j][0][0][0], 65536, sb + SO_FULL + 8u * j);
        }
    }

    float b17v = b17[0];

    // ---- fc1: build A fragments (16 rows per warp) directly in registers ----
    size_t p0 = (size_t)blockIdx.x * 128 + (size_t)(wid * 16 + g);
    float2 xa = reinterpret_cast<const float2*>(x)[p0];       // row g
    float2 xb = reinterpret_cast<const float2*>(x)[p0 + 8];   // row g+8

    uint32_t Ahi[8][4], Alo[8][4];
#pragma unroll
    for (int kt = 0; kt < 8; kt++) {
        int c = kt * 16 + tig * 2;
        float va0 = fmaxf(fmaf(xa.x, sW1[c],     fmaf(xa.y, sW1[128 + c],     sB1[c])),     0.f);
        float va1 = fmaxf(fmaf(xa.x, sW1[c + 1], fmaf(xa.y, sW1[128 + c + 1], sB1[c + 1])), 0.f);
        float vb0 = fmaxf(fmaf(xb.x, sW1[c],     fmaf(xb.y, sW1[128 + c],     sB1[c])),     0.f);
        float vb1 = fmaxf(fmaf(xb.x, sW1[c + 1], fmaf(xb.y, sW1[128 + c + 1], sB1[c + 1])), 0.f);
        float va2 = fmaxf(fmaf(xa.x, sW1[c + 8], fmaf(xa.y, sW1[128 + c + 8], sB1[c + 8])), 0.f);
        float va3 = fmaxf(fmaf(xa.x, sW1[c + 9], fmaf(xa.y, sW1[128 + c + 9], sB1[c + 9])), 0.f);
        float vb2 = fmaxf(fmaf(xb.x, sW1[c + 8], fmaf(xb.y, sW1[128 + c + 8], sB1[c + 8])), 0.f);
        float vb3 = fmaxf(fmaf(xb.x, sW1[c + 9], fmaf(xb.y, sW1[128 + c + 9], sB1[c + 9])), 0.f);
        split2(va0, va1, Ahi[kt][0], Alo[kt][0]);
        split2(vb0, vb1, Ahi[kt][1], Alo[kt][1]);
        split2(va2, va3, Ahi[kt][2], Alo[kt][2]);
        split2(vb2, vb3, Ahi[kt][3], Alo[kt][3]);
    }

    // seed warp-phase stagger so epilogues of some warps overlap MMAs of others
    if (wid) __nanosleep((unsigned)(wid * 250));

    float D[16][4];

    for (int i = 0; i < NLAYER; i++) {
        // init D with this layer's bias (D = bias + A@W)
        const float* bi = sBias + i * 128 + tig * 2;
#pragma unroll
        for (int nt = 0; nt < 16; nt++) {
            float2 bb = *reinterpret_cast<const float2*>(bi + nt * 8);
            D[nt][0] = bb.x; D[nt][1] = bb.y; D[nt][2] = bb.x; D[nt][3] = bb.y;
        }

        int buf = i % NBUF;
        mbar_wait(sb + SO_FULL + 8u * buf, (uint32_t)((i / NBUF) & 1));
        uint32_t wb = sb + SO_WBUF + (uint32_t)buf * 65536u + (uint32_t)lane * 16u;

        // 3-pass split-bf16 GEMM: D += Ahi*Whi + Alo*Whi + Ahi*Wlo
#pragma unroll
        for (int kt = 0; kt < 8; kt++) {
#pragma unroll
            for (int nt2 = 0; nt2 < 8; nt2++) {
                uint32_t off = (uint32_t)((kt * 8 + nt2) * 512);
                uint4 whi = lds128(wb + off);
                uint4 wlo = lds128(wb + 32768u + off);
                mma16816(D[2 * nt2],     Ahi[kt], whi.x, whi.y);
                mma16816(D[2 * nt2 + 1], Ahi[kt], whi.z, whi.w);
                mma16816(D[2 * nt2],     Alo[kt], whi.x, whi.y);
                mma16816(D[2 * nt2 + 1], Alo[kt], whi.z, whi.w);
                mma16816(D[2 * nt2],     Ahi[kt], wlo.x, wlo.y);
                mma16816(D[2 * nt2 + 1], Ahi[kt], wlo.z, wlo.w);
            }
        }

        // this warp is done reading buffer `buf` for layer i; last warp triggers prefetch
        if (lane == 0) {
            uint32_t old = atom_inc_acqrel(sb + SO_CNT + 4u * i);
            if (old == 7 && i + NBUF < NLAYER) {
                asm volatile("fence.proxy.async.shared::cta;" ::: "memory");
                uint32_t fb = sb + SO_FULL + 8u * buf;
                mbar_expect_tx(fb, 65536);
                bulk_g2s(sb + SO_WBUF + (uint32_t)buf * 65536u,
                         &g_wfrag[i + NBUF][0][0][0], 65536, fb);
            }
        }

        if (i < NLAYER - 1) {
            // epilogue: relu + register-local repack D -> next A fragments
#pragma unroll
            for (int nt = 0; nt < 16; nt++) {
                float v0 = fmaxf(D[nt][0], 0.f);
                float v1 = fmaxf(D[nt][1], 0.f);
                float v2 = fmaxf(D[nt][2], 0.f);
                float v3 = fmaxf(D[nt][3], 0.f);
                int kt = nt >> 1, rp = (nt & 1) * 2;
                split2(v0, v1, Ahi[kt][rp],     Alo[kt][rp]);
                split2(v2, v3, Ahi[kt][rp + 1], Alo[kt][rp + 1]);
            }
        } else {
            // fc17: dot with W17 + shfl reduce over the 4-lane column groups
            const float* w7 = sW17 + tig * 2;
            float s0 = 0.f, s1 = 0.f;
#pragma unroll
            for (int nt = 0; nt < 16; nt++) {
                float2 w2 = *reinterpret_cast<const float2*>(w7 + nt * 8);
                float v0 = fmaxf(D[nt][0], 0.f);
                float v1 = fmaxf(D[nt][1], 0.f);
                float v2 = fmaxf(D[nt][2], 0.f);
                float v3 = fmaxf(D[nt][3], 0.f);
                s0 = fmaf(v0, w2.x, fmaf(v1, w2.y, s0));
                s1 = fmaf(v2, w2.x, fmaf(v3, w2.y, s1));
            }
            s0 += __shfl_xor_sync(0xFFFFFFFFu, s0, 1);
            s0 += __shfl_xor_sync(0xFFFFFFFFu, s0, 2);
            s1 += __shfl_xor_sync(0xFFFFFFFFu, s1, 1);
            s1 += __shfl_xor_sync(0xFFFFFFFFu, s1, 2);
            if (tig == 0) {
                out[p0]     = s0 + b17v;
                out[p0 + 8] = s1 + b17v;
            }
        }
    }
}

// ---------------- launch ----------------
extern "C" void kernel_launch(void* const* d_in, const int* in_sizes, int n_in,
                              void* d_out, int out_size) {
    const float* x   = (const float*)d_in[0];
    const float* W1  = (const float*)d_in[1];
    const float* b1  = (const float*)d_in[2];
    const float* Ws  = (const float*)d_in[3];
    const float* bs  = (const float*)d_in[4];
    const float* W17 = (const float*)d_in[5];
    const float* b17 = (const float*)d_in[6];
    float* out = (float*)d_out;

    cudaFuncSetAttribute(mlp_kernel, cudaFuncAttributeMaxDynamicSharedMemorySize, SMEM_TOTAL);

    int npts = in_sizes[0] / 2;
    int nblk = npts / 128;

    prep_weights<<<(NLAYER * 2 * 64 * 32 + 255) / 256, 256>>>(Ws);
    mlp_kernel<<<nblk, 256, SMEM_TOTAL>>>(x, W1, b1, bs, W17, b17, out);
}